// round 1
// baseline (speedup 1.0000x reference)
#include <cuda_runtime.h>
#include <cuda_bf16.h>
#include <cub/cub.cuh>
#include <math.h>

#define Hh 128
#define Ww 128
#define NPIX 16384
#define NANCH 9
#define NTOT 147456   // NPIX * 9
#define MAXOUT 300

// ---------------- static device scratch (no allocations allowed) -------------
__device__ float g_buf1[NPIX * 512];     // relu(conv1 out)
__device__ float g_buf2[NPIX * 512];     // conv2 out
__device__ float g_wcomb[512 * 48];      // combined 1x1 head weights (9 score + 36 box + 3 pad)
__device__ float g_bcomb[48];
__device__ float g_hout[NPIX * 48];
__device__ float4 g_boxes[NTOT];
__device__ float g_scores[NTOT];
__device__ int   g_vals[NTOT];
__device__ float g_skeys[NTOT];
__device__ int   g_svals[NTOT];
__device__ unsigned char g_cubtemp[32u << 20];

// ---------------- conv 3x3 as implicit GEMM (fp32, 128x128x32 tile) ----------
// out[pixel, n] = sum_{tap,c} act(in[y+dy, x+dx, c]) * w[(tap*CIN+c)*512 + n]
template <int CIN, bool RELU_IN, bool RELU_OUT>
__global__ void __launch_bounds__(256, 2)
conv3x3_kernel(const float* __restrict__ in, const float* __restrict__ w,
               const float* __restrict__ bias, float* __restrict__ out)
{
    __shared__ float As[32][132];
    __shared__ float Bs[32][132];

    const int tid = threadIdx.x;
    const int n0  = blockIdx.x * 128;   // output-channel block (N=512 -> 4 blocks)
    const int y   = blockIdx.y;         // one image row = 128 pixels (M tile)
    const int tx  = tid & 15;
    const int ty  = tid >> 4;

    float acc[8][8];
    #pragma unroll
    for (int i = 0; i < 8; i++)
        #pragma unroll
        for (int j = 0; j < 8; j++) acc[i][j] = 0.f;

    const int K = 9 * CIN;
    for (int k0 = 0; k0 < K; k0 += 32) {
        const int tap = k0 / CIN;
        const int c0  = k0 - tap * CIN;       // 32 | CIN, so chunk stays in one tap
        const int dy  = tap / 3 - 1;
        const int dx  = tap % 3 - 1;
        const int ysrc = y + dy;
        const bool yok = (ysrc >= 0) && (ysrc < Hh);

        // A tile: 128 pixels x 32 channels  (1024 float4, 4 per thread)
        #pragma unroll
        for (int r = 0; r < 4; r++) {
            int item = tid + r * 256;
            int p  = item >> 3;         // pixel in row
            int cg = item & 7;          // float4 group within 32 channels
            int xsrc = p + dx;
            float4 v = make_float4(0.f, 0.f, 0.f, 0.f);
            if (yok && xsrc >= 0 && xsrc < Ww) {
                v = *(const float4*)(in + ((size_t)((ysrc << 7) + xsrc)) * CIN + c0 + cg * 4);
                if (RELU_IN) {
                    v.x = fmaxf(v.x, 0.f); v.y = fmaxf(v.y, 0.f);
                    v.z = fmaxf(v.z, 0.f); v.w = fmaxf(v.w, 0.f);
                }
            }
            As[cg * 4 + 0][p] = v.x;
            As[cg * 4 + 1][p] = v.y;
            As[cg * 4 + 2][p] = v.z;
            As[cg * 4 + 3][p] = v.w;
        }

        // B tile: 32 k x 128 n
        #pragma unroll
        for (int r = 0; r < 4; r++) {
            int item = tid + r * 256;
            int kk = item >> 5;
            int ng = item & 31;
            float4 v = *(const float4*)(w + (size_t)(k0 + kk) * 512 + n0 + ng * 4);
            *(float4*)&Bs[kk][ng * 4] = v;
        }

        __syncthreads();

        #pragma unroll
        for (int kk = 0; kk < 32; kk++) {
            float a[8], b[8];
            *(float4*)(a)     = *(const float4*)&As[kk][ty * 8];
            *(float4*)(a + 4) = *(const float4*)&As[kk][ty * 8 + 4];
            *(float4*)(b)     = *(const float4*)&Bs[kk][tx * 8];
            *(float4*)(b + 4) = *(const float4*)&Bs[kk][tx * 8 + 4];
            #pragma unroll
            for (int i = 0; i < 8; i++)
                #pragma unroll
                for (int j = 0; j < 8; j++)
                    acc[i][j] += a[i] * b[j];
        }
        __syncthreads();
    }

    // epilogue: + bias, optional relu
    #pragma unroll
    for (int i = 0; i < 8; i++) {
        int gp = (y << 7) + ty * 8 + i;
        float* op = out + (size_t)gp * 512 + n0 + tx * 8;
        #pragma unroll
        for (int j = 0; j < 8; j++) {
            float v = acc[i][j] + bias[n0 + tx * 8 + j];
            if (RELU_OUT) v = fmaxf(v, 0.f);
            op[j] = v;
        }
    }
}

// ---------------- combine 1x1 head weights into [512,48] ---------------------
__global__ void prep_w_kernel(const float* __restrict__ ws, const float* __restrict__ bs,
                              const float* __restrict__ wb, const float* __restrict__ bb,
                              float* __restrict__ wcomb, float* __restrict__ bcomb)
{
    int i = blockIdx.x * 256 + threadIdx.x;
    if (i < 512 * 48) {
        int c = i / 48, o = i - c * 48;
        float v = 0.f;
        if (o < 9)       v = ws[c * 9 + o];
        else if (o < 45) v = wb[c * 36 + (o - 9)];
        wcomb[i] = v;
    }
    if (i < 48) {
        float v = 0.f;
        if (i < 9)       v = bs[i];
        else if (i < 45) v = bb[i - 9];
        bcomb[i] = v;
    }
}

// ---------------- 1x1 head: [16384,512] x [512,48] ---------------------------
__global__ void head_kernel(const float* __restrict__ x, const float* __restrict__ w,
                            const float* __restrict__ b, float* __restrict__ hout)
{
    __shared__ float xs[4][512];
    const int tid = threadIdx.x;
    const int p0 = blockIdx.x * 4;
    #pragma unroll
    for (int r = 0; r < 2; r++) {
        int item = tid + r * 256;
        int p = item >> 7, c4 = item & 127;
        *(float4*)&xs[p][c4 * 4] = ((const float4*)(x + (size_t)(p0 + p) * 512))[c4];
    }
    __syncthreads();
    if (tid < 192) {
        int p = tid / 48, o = tid - (tid / 48) * 48;
        float acc = b[o];
        #pragma unroll 8
        for (int c = 0; c < 512; c++)
            acc += xs[p][c] * w[c * 48 + o];
        hout[(size_t)(p0 + p) * 48 + o] = acc;
    }
}

// ---------------- decode + sigmoid + anchors ---------------------------------
__global__ void decode_kernel(const float* __restrict__ hout, float4* __restrict__ boxes,
                              float* __restrict__ scores, int* __restrict__ vals)
{
    int t = blockIdx.x * 256 + threadIdx.x;
    if (t >= NTOT) return;
    int p = t / 9, a = t - p * 9;
    int yy = p >> 7, xx = p & 127;
    int s_i = a / 3, r_i = a - s_i * 3;
    float scale = (s_i == 0) ? 128.f : ((s_i == 1) ? 256.f : 512.f);
    float ratio = (r_i == 0) ? 0.5f : ((r_i == 1) ? 1.f : 2.f);
    float sr = sqrtf(ratio);
    float ah = scale * sr;
    float aw = scale / sr;
    float acy = ((float)yy + 0.5f) * 16.f;
    float acx = ((float)xx + 0.5f) * 16.f;

    const float* hp = hout + (size_t)p * 48;
    float logit = hp[a];
    float dy = hp[9 + a * 4 + 0];
    float dx = hp[9 + a * 4 + 1];
    float dh = hp[9 + a * 4 + 2];
    float dw = hp[9 + a * 4 + 3];

    float cy = acy + dy * ah;
    float cx = acx + dx * aw;
    float h = ah * expf(dh);
    float w = aw * expf(dw);
    const float LIM = 2048.f;
    float y1 = fminf(fmaxf(cy - 0.5f * h, 0.f), LIM);
    float x1 = fminf(fmaxf(cx - 0.5f * w, 0.f), LIM);
    float y2 = fminf(fmaxf(cy + 0.5f * h, 0.f), LIM);
    float x2 = fminf(fmaxf(cx + 0.5f * w, 0.f), LIM);

    boxes[t] = make_float4(y1, x1, y2, x2);
    scores[t] = 1.f / (1.f + expf(-logit));
    vals[t] = t;
}

// ---------------- greedy NMS on sorted candidates ----------------------------
__device__ __forceinline__ float iou_f(float4 a, float4 b)
{
    float areaA = (a.z - a.x) * (a.w - a.y);
    float areaB = (b.z - b.x) * (b.w - b.y);
    float iy = fmaxf(0.f, fminf(a.z, b.z) - fmaxf(a.x, b.x));
    float ix = fmaxf(0.f, fminf(a.w, b.w) - fmaxf(a.y, b.y));
    float inter = iy * ix;
    return inter / (areaA + areaB - inter + 1e-9f);
}

__global__ void nms_kernel(const float* __restrict__ skeys, const int* __restrict__ svals,
                           const float4* __restrict__ boxes, float* __restrict__ out,
                           int out_size)
{
    __shared__ float4 abox[MAXOUT];
    __shared__ float ascore[MAXOUT];
    __shared__ float4 cbox[32];
    __shared__ float cscore[32];
    __shared__ unsigned int crossmask;
    __shared__ unsigned int validmask;
    __shared__ unsigned int supmask[32];
    __shared__ int s_count;
    __shared__ int s_done;

    const int tid = threadIdx.x;
    if (tid == 0) { s_count = 0; s_done = 0; }
    __syncthreads();

    for (int base = 0; ; base += 32) {
        if (tid < 32) {
            supmask[tid] = 0u;
            if (tid == 0) { crossmask = 0u; validmask = 0u; }
        }
        __syncthreads();

        if (tid < 32) {
            int j = base + tid;
            float s = (j < NTOT) ? skeys[j] : -1.f;
            cscore[tid] = s;
            if (s >= 0.5f) {
                atomicOr(&validmask, 1u << tid);
                cbox[tid] = boxes[svals[j]];
            } else {
                cbox[tid] = make_float4(0.f, 0.f, 0.f, 0.f);
            }
        }
        __syncthreads();

        const int cnt = s_count;
        // cross: candidate c vs accepted list (32 groups over accepted)
        {
            int c = tid & 31, g = tid >> 5;
            if (validmask & (1u << c)) {
                float4 b = cbox[c];
                for (int a = g; a < cnt; a += 32) {
                    if (iou_f(b, abox[a]) > 0.7f) { atomicOr(&crossmask, 1u << c); break; }
                }
            }
        }
        // intra: pair (c, d), d > c
        {
            int c = tid >> 5, d = tid & 31;
            if (d > c && (validmask & (1u << c)) && (validmask & (1u << d))) {
                if (iou_f(cbox[c], cbox[d]) > 0.7f) atomicOr(&supmask[c], 1u << d);
            }
        }
        __syncthreads();

        if (tid == 0) {
            unsigned int alive = validmask & ~crossmask;
            int count = s_count;
            for (int c = 0; c < 32; c++) {
                if (cscore[c] < 0.5f) { s_done = 1; break; }  // sorted: all later lower
                if (!(alive & (1u << c))) continue;
                abox[count] = cbox[c];
                ascore[count] = cscore[c];
                count++;
                if (count == MAXOUT) { s_done = 1; break; }
                alive &= ~supmask[c];
            }
            s_count = count;
            if (base + 32 >= NTOT) s_done = 1;
        }
        __syncthreads();
        if (s_done) break;
    }

    // write output: [boxes 300x4][scores 300][valid 300] as float32
    const int cnt = s_count;
    for (int i = tid; i < MAXOUT; i += blockDim.x) {
        float4 b = make_float4(0.f, 0.f, 0.f, 0.f);
        float sc = 0.f, vf = 0.f;
        if (i < cnt) { b = abox[i]; sc = ascore[i]; vf = 1.f; }
        if (i * 4 + 3 < out_size) {
            out[i * 4 + 0] = b.x; out[i * 4 + 1] = b.y;
            out[i * 4 + 2] = b.z; out[i * 4 + 3] = b.w;
        }
        if (1200 + i < out_size) out[1200 + i] = sc;
        if (1500 + i < out_size) out[1500 + i] = vf;
    }
}

// ---------------- launcher ---------------------------------------------------
extern "C" void kernel_launch(void* const* d_in, const int* in_sizes, int n_in,
                              void* d_out, int out_size)
{
    const float* features = (const float*)d_in[0];
    const float* w1       = (const float*)d_in[1];
    const float* b1       = (const float*)d_in[2];
    const float* w2       = (const float*)d_in[3];
    const float* b2       = (const float*)d_in[4];
    const float* w_score  = (const float*)d_in[5];
    const float* b_score  = (const float*)d_in[6];
    const float* w_box    = (const float*)d_in[7];
    const float* b_box    = (const float*)d_in[8];

    float *buf1, *buf2, *wcomb, *bcomb, *hout, *scores, *skeys;
    float4* boxes;
    int *vals, *svals;
    unsigned char* cubtemp;
    cudaGetSymbolAddress((void**)&buf1, g_buf1);
    cudaGetSymbolAddress((void**)&buf2, g_buf2);
    cudaGetSymbolAddress((void**)&wcomb, g_wcomb);
    cudaGetSymbolAddress((void**)&bcomb, g_bcomb);
    cudaGetSymbolAddress((void**)&hout, g_hout);
    cudaGetSymbolAddress((void**)&boxes, g_boxes);
    cudaGetSymbolAddress((void**)&scores, g_scores);
    cudaGetSymbolAddress((void**)&vals, g_vals);
    cudaGetSymbolAddress((void**)&skeys, g_skeys);
    cudaGetSymbolAddress((void**)&svals, g_svals);
    cudaGetSymbolAddress((void**)&cubtemp, g_cubtemp);

    prep_w_kernel<<<(512 * 48 + 255) / 256, 256>>>(w_score, b_score, w_box, b_box, wcomb, bcomb);

    dim3 cgrid(4, 128);
    conv3x3_kernel<1024, true, true><<<cgrid, 256>>>(features, w1, b1, buf1);
    conv3x3_kernel<512, false, false><<<cgrid, 256>>>(buf1, w2, b2, buf2);

    head_kernel<<<NPIX / 4, 256>>>(buf2, wcomb, bcomb, hout);
    decode_kernel<<<(NTOT + 255) / 256, 256>>>(hout, boxes, scores, vals);

    size_t temp_bytes = 0;
    cub::DeviceRadixSort::SortPairsDescending(nullptr, temp_bytes,
                                              scores, skeys, vals, svals, NTOT);
    if (temp_bytes > (32u << 20)) temp_bytes = (32u << 20);
    cub::DeviceRadixSort::SortPairsDescending((void*)cubtemp, temp_bytes,
                                              scores, skeys, vals, svals, NTOT);

    nms_kernel<<<1, 1024>>>(skeys, svals, boxes, (float*)d_out, out_size);
}